// round 5
// baseline (speedup 1.0000x reference)
#include <cuda_runtime.h>

#define NCLS 19
#define CH   256
#define HW   16384      // 128*128
#define HW4  (HW/4)     // 4096
#define BSZ  8
#define NPIX (BSZ*HW)   // 131072
#define NQ   2975
#define INV_T 5.0f      // 1/0.2
#define CPT  2          // channels per block in sums kernel

#define PRED_BLOCKS (NPIX/4/256)     // 128
#define SUMS_BLOCKS ((CH/CPT)*BSZ)   // 1024
#define LSE_SPLIT   2
#define LSE_BLOCKS  (CH*LSE_SPLIT)   // 512

// ---- device scratch (zero-initialized at load; tickets/loss self-reset) ----
__device__ float          g_partial[BSZ*NCLS*CH];   // per-(b) class sums
__device__ int            g_hist[PRED_BLOCKS*NCLS]; // per-pred-block counts
__device__ int            g_counts[NCLS];
__device__ float          g_keys[NCLS*CH];
__device__ unsigned char  g_pred[NPIX];
__device__ float          g_loss;
__device__ int            g_t1, g_t2;

// pack two floats into a .b64 register pair (lo = a, hi = b)
#define PACKF2(D, A, B) \
    asm("mov.b64 %0, {%1, %2};" : "=l"(D) : "r"(__float_as_uint(A)), "r"(__float_as_uint(B)))

// predicated packed-f32x2 accumulate: if (pk==k) acc += v  (v = {ch0, ch1})
#define MASKED_ADD1(ACC, PK, K, V)                                          \
    asm volatile("{\n\t.reg .pred p;\n\t"                                   \
                 "setp.eq.s32 p, %1, %2;\n\t"                               \
                 "@p add.rn.f32x2 %0, %0, %3;\n\t}"                         \
                 : "+l"(ACC)                                                \
                 : "r"(PK), "r"(K), "l"(V))

__device__ __forceinline__ float u64_lo_f(unsigned long long x) {
    return __uint_as_float((unsigned)(x & 0xffffffffull));
}
__device__ __forceinline__ float u64_hi_f(unsigned long long x) {
    return __uint_as_float((unsigned)(x >> 32));
}

// ---------------------------------------------------------------------------
// pred: argmax over classes (x4 vectorized) + copy res -> out + block hist
// ---------------------------------------------------------------------------
__global__ void __launch_bounds__(256) pred_kernel(const float4* __restrict__ res4,
                                                   float4* __restrict__ out4) {
    __shared__ int hist[NCLS];
    int tid = threadIdx.x;
    if (tid < NCLS) hist[tid] = 0;
    __syncthreads();

    int t4 = blockIdx.x * 256 + tid;       // quad index
    int b  = t4 >> 12;                     // / HW4
    int p4 = t4 & (HW4 - 1);
    const float4* r = res4 + (size_t)b * NCLS * HW4 + p4;
    float4*       o = out4 + (size_t)b * NCLS * HW4 + p4;

    float4 best = r[0];
    o[0] = best;
    int bk0 = 0, bk1 = 0, bk2 = 0, bk3 = 0;
    #pragma unroll
    for (int k = 1; k < NCLS; k++) {
        float4 v = r[(size_t)k * HW4];
        o[(size_t)k * HW4] = v;
        if (v.x > best.x) { best.x = v.x; bk0 = k; }
        if (v.y > best.y) { best.y = v.y; bk1 = k; }
        if (v.z > best.z) { best.z = v.z; bk2 = k; }
        if (v.w > best.w) { best.w = v.w; bk3 = k; }
    }
    ((uchar4*)g_pred)[t4] = make_uchar4((unsigned char)bk0, (unsigned char)bk1,
                                        (unsigned char)bk2, (unsigned char)bk3);
    atomicAdd(&hist[bk0], 1);
    atomicAdd(&hist[bk1], 1);
    atomicAdd(&hist[bk2], 1);
    atomicAdd(&hist[bk3], 1);
    __syncthreads();
    if (tid < NCLS) g_hist[blockIdx.x * NCLS + tid] = hist[tid];
}

// ---------------------------------------------------------------------------
// sums: per-class masked sum of fea (predicated packed f32x2).
// Block (2-ch group, batch) writes partials plainly (no atomics).
// Last block (ticket) reduces over batch, computes counts + normalized keys.
// ---------------------------------------------------------------------------
__global__ void __launch_bounds__(256, 2) sums_kernel(const float* __restrict__ fea) {
    int b  = blockIdx.y;
    int c0 = blockIdx.x * CPT;

    unsigned long long acc[NCLS];
    #pragma unroll
    for (int k = 0; k < NCLS; k++) acc[k] = 0ull;

    const float4* f0 = (const float4*)(fea + (size_t)(b * CH + c0 + 0) * HW);
    const float4* f1 = (const float4*)(fea + (size_t)(b * CH + c0 + 1) * HW);
    const uchar4* pr = (const uchar4*)(g_pred + b * HW);

    #pragma unroll 2
    for (int p4 = threadIdx.x; p4 < HW4; p4 += 256) {
        uchar4 pq = pr[p4];
        float4 v0 = f0[p4], v1 = f1[p4];
        int pk0 = pq.x, pk1 = pq.y, pk2 = pq.z, pk3 = pq.w;

        unsigned long long x0, x1, x2, x3;   // {ch0, ch1} per pixel
        PACKF2(x0, v0.x, v1.x);
        PACKF2(x1, v0.y, v1.y);
        PACKF2(x2, v0.z, v1.z);
        PACKF2(x3, v0.w, v1.w);

        #pragma unroll
        for (int k = 0; k < NCLS; k++) {
            MASKED_ADD1(acc[k], pk0, k, x0);
            MASKED_ADD1(acc[k], pk1, k, x1);
            MASKED_ADD1(acc[k], pk2, k, x2);
            MASKED_ADD1(acc[k], pk3, k, x3);
        }
    }

    // block reduce: warp shfl -> smem across warps -> plain store of partials
    __shared__ float wsum[8][NCLS * CPT];
    int lane = threadIdx.x & 31;
    int wid  = threadIdx.x >> 5;

    #pragma unroll
    for (int k = 0; k < NCLS; k++) {
        float s0 = u64_lo_f(acc[k]);
        float s1 = u64_hi_f(acc[k]);
        #pragma unroll
        for (int o = 16; o; o >>= 1) {
            s0 += __shfl_down_sync(0xffffffffu, s0, o);
            s1 += __shfl_down_sync(0xffffffffu, s1, o);
        }
        if (lane == 0) {
            wsum[wid][k * CPT + 0] = s0;
            wsum[wid][k * CPT + 1] = s1;
        }
    }
    __syncthreads();
    if (threadIdx.x < NCLS * CPT) {
        int j = threadIdx.x;
        float s = 0.0f;
        #pragma unroll
        for (int w = 0; w < 8; w++) s += wsum[w][j];
        int k = j / CPT, i = j % CPT;
        g_partial[(size_t)(b * NCLS + k) * CH + c0 + i] = s;   // plain store
        __threadfence();
    }
    __syncthreads();

    // ---- ticket: last block computes counts + keys ----
    __shared__ int s_last;
    if (threadIdx.x == 0)
        s_last = (atomicAdd(&g_t1, 1) == SUMS_BLOCKS - 1) ? 1 : 0;
    __syncthreads();
    if (!s_last) return;
    __threadfence();

    __shared__ float kv[NCLS * CH];      // 19 KB: per-class mean vectors
    __shared__ float scnt[NCLS];
    __shared__ float red[8];
    __shared__ float snorm[NCLS];
    int tid = threadIdx.x;

    if (tid < NCLS) {
        int s = 0;
        for (int pb = 0; pb < PRED_BLOCKS; pb++) s += g_hist[pb * NCLS + tid];
        g_counts[tid] = s;
        scnt[tid] = (float)max(s, 1);
    }
    __syncthreads();

    for (int kc = tid; kc < NCLS * CH; kc += 256) {
        int k = kc >> 8, c = kc & 255;
        float s = 0.0f;
        #pragma unroll
        for (int bb = 0; bb < BSZ; bb++)
            s += g_partial[(size_t)(bb * NCLS + k) * CH + c];
        kv[kc] = s / scnt[k];
    }
    __syncthreads();

    for (int k = 0; k < NCLS; k++) {
        float v  = kv[k * CH + tid];
        float ss = v * v;
        #pragma unroll
        for (int o = 16; o; o >>= 1) ss += __shfl_xor_sync(0xffffffffu, ss, o);
        if ((tid & 31) == 0) red[tid >> 5] = ss;
        __syncthreads();
        if (tid == 0) {
            float t = red[0] + red[1] + red[2] + red[3] +
                      red[4] + red[5] + red[6] + red[7];
            snorm[k] = fmaxf(sqrtf(t), 1e-12f);
        }
        __syncthreads();
    }

    for (int kc = tid; kc < NCLS * CH; kc += 256)
        g_keys[kc] = kv[kc] / snorm[kc >> 8];

    if (tid == 0) g_t1 = 0;    // self-reset for next replay
}

// ---------------------------------------------------------------------------
// fused qsum + lse (single-pass, m=0 — logits are O(1) for normalized data):
// grid (CH, 2). Phase A builds qsum row in smem; phase B: half the classes.
// Loss finalized by last-arriving block (self-resetting g_loss/g_t2).
// ---------------------------------------------------------------------------
__global__ void __launch_bounds__(256) lse_kernel(const float* __restrict__ queues,
                                                  float* __restrict__ out_loss) {
    __shared__ float qs[NQ];          // 11.9 KB qsum row for this c
    __shared__ float red[8];

    int c   = blockIdx.x;
    int tid = threadIdx.x;
    int k0  = blockIdx.y * 10;        // [0,10) and [10,19)
    int k1  = min(k0 + 10, NCLS);

    // Phase A: qsum[c][j] = sum_k queues[k][c][j]
    {
        float s[12];
        #pragma unroll
        for (int i = 0; i < 12; i++) s[i] = 0.0f;
        for (int k = 0; k < NCLS; k++) {
            const float* row = queues + ((size_t)(k * CH + c)) * NQ;
            #pragma unroll
            for (int i = 0; i < 12; i++) {
                int j = tid + i * 256;
                if (j < NQ) s[i] += row[j];
            }
        }
        #pragma unroll
        for (int i = 0; i < 12; i++) {
            int j = tid + i * 256;
            if (j < NQ) qs[j] = s[i];
        }
    }
    __syncthreads();

    float loss_acc = 0.0f;            // meaningful on tid 0 only

    for (int k = k0; k < k1; k++) {
        float a = g_keys[k * CH + c] * INV_T;
        const float* row = queues + ((size_t)(k * CH + c)) * NQ;

        float s = 0.0f;
        float logit0 = 0.0f;
        #pragma unroll
        for (int i = 0; i < 12; i++) {
            int j = tid + i * 256;
            if (j < NQ) {
                float q  = row[j];
                float x1 = a * q;
                float x2 = a * (qs[j] - q);
                s += __expf(x1) + __expf(x2);
                if (i == 0 && tid == 0) logit0 = x1;   // j==0
            }
        }

        __syncthreads();              // protect red[] from previous k
        #pragma unroll
        for (int o = 16; o; o >>= 1) s += __shfl_xor_sync(0xffffffffu, s, o);
        if ((tid & 31) == 0) red[tid >> 5] = s;
        __syncthreads();
        if (tid == 0) {
            float tot = red[0] + red[1] + red[2] + red[3] +
                        red[4] + red[5] + red[6] + red[7];
            if (g_counts[k] > 0)
                loss_acc += (__logf(tot) - logit0) * (1.0f / (float)CH);
        }
    }

    // ---- finalize loss: ticket; last block writes + resets ----
    __shared__ int s_last;
    if (tid == 0) {
        atomicAdd(&g_loss, loss_acc);
        __threadfence();
        s_last = (atomicAdd(&g_t2, 1) == LSE_BLOCKS - 1) ? 1 : 0;
    }
    __syncthreads();
    if (s_last && tid == 0) {
        __threadfence();
        float total = *((volatile float*)&g_loss);
        *out_loss = total;
        g_loss = 0.0f;
        g_t2   = 0;
    }
}

// ---------------------------------------------------------------------------
extern "C" void kernel_launch(void* const* d_in, const int* in_sizes, int n_in,
                              void* d_out, int out_size) {
    const float *fea = nullptr, *res = nullptr, *queues = nullptr;
    for (int i = 0; i < n_in; i++) {
        if (in_sizes[i] == BSZ * CH * HW)        fea    = (const float*)d_in[i];
        else if (in_sizes[i] == BSZ * NCLS * HW) res    = (const float*)d_in[i];
        else if (in_sizes[i] == NCLS * CH * NQ)  queues = (const float*)d_in[i];
    }
    float* out      = (float*)d_out;
    float* out_loss = out + (size_t)BSZ * NCLS * HW;

    pred_kernel<<<PRED_BLOCKS, 256>>>((const float4*)res, (float4*)out);
    sums_kernel<<<dim3(CH / CPT, BSZ), 256>>>(fea);
    lse_kernel<<<dim3(CH, LSE_SPLIT), 256>>>(queues, out_loss);
}

// round 8
// speedup vs baseline: 1.1932x; 1.1932x over previous
#include <cuda_runtime.h>

#define NCLS 19
#define CH   256
#define HW   16384      // 128*128
#define HW4  (HW/4)     // 4096
#define BSZ  8
#define NPIX (BSZ*HW)   // 131072
#define NQ   2975
#define INV_T 5.0f      // 1/0.2
#define CPT  2          // channels per block in sums kernel

#define PRED_BLOCKS (NPIX/4/256)     // 128
#define LSE_SPLIT   2

// ---- device scratch (fully rewritten every launch sequence) ----
__device__ float          g_sums[NCLS*CH];
__device__ int            g_hist[PRED_BLOCKS*NCLS]; // per-pred-block counts
__device__ int            g_counts[NCLS];
__device__ float          g_keys[NCLS*CH];
__device__ unsigned char  g_pred[NPIX];

// pack two floats into a .b64 register pair (lo = a, hi = b)
#define PACKF2(D, A, B) \
    asm("mov.b64 %0, {%1, %2};" : "=l"(D) : "r"(__float_as_uint(A)), "r"(__float_as_uint(B)))

// predicated packed-f32x2 accumulate: if (pk==k) acc += v  (v = {ch0, ch1})
#define MASKED_ADD1(ACC, PK, K, V)                                          \
    asm volatile("{\n\t.reg .pred p;\n\t"                                   \
                 "setp.eq.s32 p, %1, %2;\n\t"                               \
                 "@p add.rn.f32x2 %0, %0, %3;\n\t}"                         \
                 : "+l"(ACC)                                                \
                 : "r"(PK), "r"(K), "l"(V))

__device__ __forceinline__ float u64_lo_f(unsigned long long x) {
    return __uint_as_float((unsigned)(x & 0xffffffffull));
}
__device__ __forceinline__ float u64_hi_f(unsigned long long x) {
    return __uint_as_float((unsigned)(x >> 32));
}

// ---------------------------------------------------------------------------
// pred: argmax over classes (x4 vectorized) + copy res -> out + block hist.
// Also zeroes g_sums and the loss slot (kernel boundary = visibility).
// ---------------------------------------------------------------------------
__global__ void __launch_bounds__(256) pred_kernel(const float4* __restrict__ res4,
                                                   float4* __restrict__ out4,
                                                   float* __restrict__ out_loss) {
    __shared__ int hist[NCLS];
    int tid = threadIdx.x;
    if (tid < NCLS) hist[tid] = 0;

    int t4 = blockIdx.x * 256 + tid;       // global quad index
    if (t4 < NCLS * CH) g_sums[t4] = 0.0f; // zero accumulator buffer
    if (t4 == 0)        *out_loss = 0.0f;  // zero loss slot
    __syncthreads();

    int b  = t4 >> 12;                     // / HW4
    int p4 = t4 & (HW4 - 1);
    const float4* r = res4 + (size_t)b * NCLS * HW4 + p4;
    float4*       o = out4 + (size_t)b * NCLS * HW4 + p4;

    float4 best = r[0];
    o[0] = best;
    int bk0 = 0, bk1 = 0, bk2 = 0, bk3 = 0;
    #pragma unroll
    for (int k = 1; k < NCLS; k++) {
        float4 v = r[(size_t)k * HW4];
        o[(size_t)k * HW4] = v;
        if (v.x > best.x) { best.x = v.x; bk0 = k; }
        if (v.y > best.y) { best.y = v.y; bk1 = k; }
        if (v.z > best.z) { best.z = v.z; bk2 = k; }
        if (v.w > best.w) { best.w = v.w; bk3 = k; }
    }
    ((uchar4*)g_pred)[t4] = make_uchar4((unsigned char)bk0, (unsigned char)bk1,
                                        (unsigned char)bk2, (unsigned char)bk3);
    atomicAdd(&hist[bk0], 1);
    atomicAdd(&hist[bk1], 1);
    atomicAdd(&hist[bk2], 1);
    atomicAdd(&hist[bk3], 1);
    __syncthreads();
    if (tid < NCLS) g_hist[blockIdx.x * NCLS + tid] = hist[tid];
}

// ---------------------------------------------------------------------------
// sums: per-class masked sum of fea (predicated packed f32x2).
// Round-4 form: NO tail work — keeps registers for the hot loop.
// ---------------------------------------------------------------------------
__global__ void __launch_bounds__(256, 2) sums_kernel(const float* __restrict__ fea) {
    int b  = blockIdx.y;
    int c0 = blockIdx.x * CPT;

    unsigned long long acc[NCLS];
    #pragma unroll
    for (int k = 0; k < NCLS; k++) acc[k] = 0ull;

    const float4* f0 = (const float4*)(fea + (size_t)(b * CH + c0 + 0) * HW);
    const float4* f1 = (const float4*)(fea + (size_t)(b * CH + c0 + 1) * HW);
    const uchar4* pr = (const uchar4*)(g_pred + b * HW);

    #pragma unroll 2
    for (int p4 = threadIdx.x; p4 < HW4; p4 += 256) {
        uchar4 pq = pr[p4];
        float4 v0 = f0[p4], v1 = f1[p4];
        int pk0 = pq.x, pk1 = pq.y, pk2 = pq.z, pk3 = pq.w;

        unsigned long long x0, x1, x2, x3;   // {ch0, ch1} per pixel
        PACKF2(x0, v0.x, v1.x);
        PACKF2(x1, v0.y, v1.y);
        PACKF2(x2, v0.z, v1.z);
        PACKF2(x3, v0.w, v1.w);

        #pragma unroll
        for (int k = 0; k < NCLS; k++) {
            MASKED_ADD1(acc[k], pk0, k, x0);
            MASKED_ADD1(acc[k], pk1, k, x1);
            MASKED_ADD1(acc[k], pk2, k, x2);
            MASKED_ADD1(acc[k], pk3, k, x3);
        }
    }

    // reduce: warp shfl -> smem across warps -> one atomicAdd per (k, ci)
    __shared__ float wsum[8][NCLS * CPT];
    int lane = threadIdx.x & 31;
    int wid  = threadIdx.x >> 5;

    #pragma unroll
    for (int k = 0; k < NCLS; k++) {
        float s0 = u64_lo_f(acc[k]);
        float s1 = u64_hi_f(acc[k]);
        #pragma unroll
        for (int o = 16; o; o >>= 1) {
            s0 += __shfl_down_sync(0xffffffffu, s0, o);
            s1 += __shfl_down_sync(0xffffffffu, s1, o);
        }
        if (lane == 0) {
            wsum[wid][k * CPT + 0] = s0;
            wsum[wid][k * CPT + 1] = s1;
        }
    }
    __syncthreads();
    if (threadIdx.x < NCLS * CPT) {
        int j = threadIdx.x;
        float s = 0.0f;
        #pragma unroll
        for (int w = 0; w < 8; w++) s += wsum[w][j];
        int k = j / CPT, i = j % CPT;
        atomicAdd(&g_sums[k * CH + c0 + i], s);
    }
}

// ---------------------------------------------------------------------------
// keys: hist->counts, masked mean + L2 normalize along C. One block per class.
// ---------------------------------------------------------------------------
__global__ void __launch_bounds__(256) keys_kernel() {
    int k = blockIdx.x;
    int c = threadIdx.x;

    __shared__ float red[8];
    __shared__ float snorm;
    __shared__ int   scnt;

    // reduce per-block histograms for this class
    int h = 0;
    for (int pb = c; pb < PRED_BLOCKS; pb += 256) h += g_hist[pb * NCLS + k];
    #pragma unroll
    for (int o = 16; o; o >>= 1) h += __shfl_xor_sync(0xffffffffu, h, o);
    if ((c & 31) == 0) red[c >> 5] = __int_as_float(h);
    __syncthreads();
    if (c == 0) {
        int t = 0;
        #pragma unroll
        for (int i = 0; i < 8; i++) t += __float_as_int(red[i]);
        g_counts[k] = t;
        scnt = max(t, 1);
    }
    __syncthreads();

    float v = g_sums[k * CH + c] / (float)scnt;

    float ss = v * v;
    #pragma unroll
    for (int o = 16; o; o >>= 1) ss += __shfl_xor_sync(0xffffffffu, ss, o);
    if ((c & 31) == 0) red[c >> 5] = ss;
    __syncthreads();
    if (c == 0) {
        float t = 0.0f;
        #pragma unroll
        for (int i = 0; i < 8; i++) t += red[i];
        snorm = fmaxf(sqrtf(t), 1e-12f);
    }
    __syncthreads();
    g_keys[k * CH + c] = v / snorm;
}

// ---------------------------------------------------------------------------
// fused qsum + lse (single-pass; logits are O(5) for normalized data):
// grid (CH, 2). Phase A builds qsum row in smem; phase B: half the classes.
// Each block atomicAdds its partial loss into out_loss (zeroed by pred).
// ---------------------------------------------------------------------------
__global__ void __launch_bounds__(256) lse_kernel(const float* __restrict__ queues,
                                                  float* __restrict__ out_loss) {
    __shared__ float qs[NQ];          // 11.9 KB qsum row for this c
    __shared__ float red[8];

    int c   = blockIdx.x;
    int tid = threadIdx.x;
    int k0  = blockIdx.y * 10;        // [0,10) and [10,19)
    int k1  = min(k0 + 10, NCLS);

    // Phase A: qsum[c][j] = sum_k queues[k][c][j]
    {
        float s[12];
        #pragma unroll
        for (int i = 0; i < 12; i++) s[i] = 0.0f;
        for (int k = 0; k < NCLS; k++) {
            const float* row = queues + ((size_t)(k * CH + c)) * NQ;
            #pragma unroll
            for (int i = 0; i < 12; i++) {
                int j = tid + i * 256;
                if (j < NQ) s[i] += row[j];
            }
        }
        #pragma unroll
        for (int i = 0; i < 12; i++) {
            int j = tid + i * 256;
            if (j < NQ) qs[j] = s[i];
        }
    }
    __syncthreads();

    float loss_acc = 0.0f;            // meaningful on tid 0 only

    for (int k = k0; k < k1; k++) {
        float a = g_keys[k * CH + c] * INV_T;
        const float* row = queues + ((size_t)(k * CH + c)) * NQ;

        float s = 0.0f;
        float logit0 = 0.0f;
        #pragma unroll
        for (int i = 0; i < 12; i++) {
            int j = tid + i * 256;
            if (j < NQ) {
                float q  = row[j];
                float x1 = a * q;
                float x2 = a * (qs[j] - q);
                s += __expf(x1) + __expf(x2);
                if (i == 0 && tid == 0) logit0 = x1;   // j==0
            }
        }

        __syncthreads();              // protect red[] from previous k
        #pragma unroll
        for (int o = 16; o; o >>= 1) s += __shfl_xor_sync(0xffffffffu, s, o);
        if ((tid & 31) == 0) red[tid >> 5] = s;
        __syncthreads();
        if (tid == 0) {
            float tot = red[0] + red[1] + red[2] + red[3] +
                        red[4] + red[5] + red[6] + red[7];
            if (g_counts[k] > 0)
                loss_acc += (__logf(tot) - logit0) * (1.0f / (float)CH);
        }
    }

    if (tid == 0) atomicAdd(out_loss, loss_acc);
}

// ---------------------------------------------------------------------------
extern "C" void kernel_launch(void* const* d_in, const int* in_sizes, int n_in,
                              void* d_out, int out_size) {
    const float *fea = nullptr, *res = nullptr, *queues = nullptr;
    for (int i = 0; i < n_in; i++) {
        if (in_sizes[i] == BSZ * CH * HW)        fea    = (const float*)d_in[i];
        else if (in_sizes[i] == BSZ * NCLS * HW) res    = (const float*)d_in[i];
        else if (in_sizes[i] == NCLS * CH * NQ)  queues = (const float*)d_in[i];
    }
    float* out      = (float*)d_out;
    float* out_loss = out + (size_t)BSZ * NCLS * HW;

    pred_kernel<<<PRED_BLOCKS, 256>>>((const float4*)res, (float4*)out, out_loss);
    sums_kernel<<<dim3(CH / CPT, BSZ), 256>>>(fea);
    keys_kernel<<<NCLS, 256>>>();
    lse_kernel<<<dim3(CH, LSE_SPLIT), 256>>>(queues, out_loss);
}

// round 9
// speedup vs baseline: 1.4113x; 1.1828x over previous
#include <cuda_runtime.h>

#define NCLS 19
#define CH   256
#define HW   16384      // 128*128
#define HW4  (HW/4)     // 4096
#define BSZ  8
#define NPIX (BSZ*HW)   // 131072
#define NQ   2975
#define INV_T 5.0f      // 1/0.2
#define LOG2E 1.44269504f
#define CPT  2          // channels per block in sums kernel

#define PRED_BLOCKS (NPIX/4/256)        // 128
#define QS_BLOCKS   ((CH*NQ+255)/256)   // 2975

// ---- device scratch (fully rewritten every launch sequence) ----
__device__ float          g_sums[NCLS*CH];
__device__ int            g_hist[PRED_BLOCKS*NCLS];
__device__ int            g_counts[NCLS];
__device__ float          g_keys[NCLS*CH];
__device__ unsigned char  g_pred[NPIX];
__device__ float          g_qsum[CH*NQ];   // 3 MB, L2-resident

// pack two floats into a .b64 register pair (lo = a, hi = b)
#define PACKF2(D, A, B) \
    asm("mov.b64 %0, {%1, %2};" : "=l"(D) : "r"(__float_as_uint(A)), "r"(__float_as_uint(B)))

// predicated packed-f32x2 accumulate: if (pk==k) acc += v.
// NOT volatile: register-only, distinct outputs -> ptxas may interleave the
// independent setp/add pairs across classes, hiding the 13-cyc pred-guard
// latency that serialized the volatile version.
#define MASKED_ADD1(ACC, PK, K, V)                                          \
    asm("{\n\t.reg .pred p;\n\t"                                            \
        "setp.eq.s32 p, %1, %2;\n\t"                                        \
        "@p add.rn.f32x2 %0, %0, %3;\n\t}"                                  \
        : "+l"(ACC)                                                         \
        : "r"(PK), "r"(K), "l"(V))

__device__ __forceinline__ float u64_lo_f(unsigned long long x) {
    return __uint_as_float((unsigned)(x & 0xffffffffull));
}
__device__ __forceinline__ float u64_hi_f(unsigned long long x) {
    return __uint_as_float((unsigned)(x >> 32));
}
__device__ __forceinline__ float ex2f(float x) {
    float r;
    asm("ex2.approx.f32 %0, %1;" : "=f"(r) : "f"(x));
    return r;
}

// ---------------------------------------------------------------------------
// pred: argmax over classes (x4 vectorized) + copy res -> out + block hist.
// Also zeroes g_sums and the loss slot (kernel boundary = visibility).
// ---------------------------------------------------------------------------
__global__ void __launch_bounds__(256) pred_kernel(const float4* __restrict__ res4,
                                                   float4* __restrict__ out4,
                                                   float* __restrict__ out_loss) {
    __shared__ int hist[NCLS];
    int tid = threadIdx.x;
    if (tid < NCLS) hist[tid] = 0;

    int t4 = blockIdx.x * 256 + tid;       // global quad index
    if (t4 < NCLS * CH) g_sums[t4] = 0.0f;
    if (t4 == 0)        *out_loss = 0.0f;
    __syncthreads();

    int b  = t4 >> 12;                     // / HW4
    int p4 = t4 & (HW4 - 1);
    const float4* r = res4 + (size_t)b * NCLS * HW4 + p4;
    float4*       o = out4 + (size_t)b * NCLS * HW4 + p4;

    float4 best = r[0];
    o[0] = best;
    int bk0 = 0, bk1 = 0, bk2 = 0, bk3 = 0;
    #pragma unroll
    for (int k = 1; k < NCLS; k++) {
        float4 v = r[(size_t)k * HW4];
        o[(size_t)k * HW4] = v;
        if (v.x > best.x) { best.x = v.x; bk0 = k; }
        if (v.y > best.y) { best.y = v.y; bk1 = k; }
        if (v.z > best.z) { best.z = v.z; bk2 = k; }
        if (v.w > best.w) { best.w = v.w; bk3 = k; }
    }
    ((uchar4*)g_pred)[t4] = make_uchar4((unsigned char)bk0, (unsigned char)bk1,
                                        (unsigned char)bk2, (unsigned char)bk3);
    atomicAdd(&hist[bk0], 1);
    atomicAdd(&hist[bk1], 1);
    atomicAdd(&hist[bk2], 1);
    atomicAdd(&hist[bk3], 1);
    __syncthreads();
    if (tid < NCLS) g_hist[blockIdx.x * NCLS + tid] = hist[tid];
}

// ---------------------------------------------------------------------------
// sums: per-class masked sum of fea (predicated packed f32x2, schedulable).
// ---------------------------------------------------------------------------
__global__ void __launch_bounds__(256, 2) sums_kernel(const float* __restrict__ fea) {
    int b  = blockIdx.y;
    int c0 = blockIdx.x * CPT;

    unsigned long long acc[NCLS];
    #pragma unroll
    for (int k = 0; k < NCLS; k++) acc[k] = 0ull;

    const float4* f0 = (const float4*)(fea + (size_t)(b * CH + c0 + 0) * HW);
    const float4* f1 = (const float4*)(fea + (size_t)(b * CH + c0 + 1) * HW);
    const uchar4* pr = (const uchar4*)(g_pred + b * HW);

    #pragma unroll 2
    for (int p4 = threadIdx.x; p4 < HW4; p4 += 256) {
        uchar4 pq = pr[p4];
        float4 v0 = f0[p4], v1 = f1[p4];
        int pk0 = pq.x, pk1 = pq.y, pk2 = pq.z, pk3 = pq.w;

        unsigned long long x0, x1, x2, x3;   // {ch0, ch1} per pixel
        PACKF2(x0, v0.x, v1.x);
        PACKF2(x1, v0.y, v1.y);
        PACKF2(x2, v0.z, v1.z);
        PACKF2(x3, v0.w, v1.w);

        #pragma unroll
        for (int k = 0; k < NCLS; k++) {
            MASKED_ADD1(acc[k], pk0, k, x0);
            MASKED_ADD1(acc[k], pk1, k, x1);
            MASKED_ADD1(acc[k], pk2, k, x2);
            MASKED_ADD1(acc[k], pk3, k, x3);
        }
    }

    // reduce: warp shfl -> smem across warps -> one atomicAdd per (k, ci)
    __shared__ float wsum[8][NCLS * CPT];
    int lane = threadIdx.x & 31;
    int wid  = threadIdx.x >> 5;

    #pragma unroll
    for (int k = 0; k < NCLS; k++) {
        float s0 = u64_lo_f(acc[k]);
        float s1 = u64_hi_f(acc[k]);
        #pragma unroll
        for (int o = 16; o; o >>= 1) {
            s0 += __shfl_down_sync(0xffffffffu, s0, o);
            s1 += __shfl_down_sync(0xffffffffu, s1, o);
        }
        if (lane == 0) {
            wsum[wid][k * CPT + 0] = s0;
            wsum[wid][k * CPT + 1] = s1;
        }
    }
    __syncthreads();
    if (threadIdx.x < NCLS * CPT) {
        int j = threadIdx.x;
        float s = 0.0f;
        #pragma unroll
        for (int w = 0; w < 8; w++) s += wsum[w][j];
        int k = j / CPT, i = j % CPT;
        atomicAdd(&g_sums[k * CH + c0 + i], s);
    }
}

// ---------------------------------------------------------------------------
// fused qsum + keys, one launch:
//   blocks [0, QS_BLOCKS): g_qsum[t] = sum_k queues[k*CH*NQ + t]
//   blocks [QS_BLOCKS, +NCLS): hist->counts, mean, L2-normalize -> g_keys
// ---------------------------------------------------------------------------
__global__ void __launch_bounds__(256) qsum_keys_kernel(const float* __restrict__ queues) {
    int bid = blockIdx.x;
    int tid = threadIdx.x;

    if (bid < QS_BLOCKS) {
        int t = bid * 256 + tid;
        if (t < CH * NQ) {
            float s = 0.0f;
            #pragma unroll
            for (int k = 0; k < NCLS; k++) s += queues[(size_t)k * CH * NQ + t];
            g_qsum[t] = s;
        }
        return;
    }

    // ---- keys part ----
    int k = bid - QS_BLOCKS;
    int c = tid;

    __shared__ float red[8];
    __shared__ float snorm;
    __shared__ int   scnt;

    int h = 0;
    for (int pb = c; pb < PRED_BLOCKS; pb += 256) h += g_hist[pb * NCLS + k];
    #pragma unroll
    for (int o = 16; o; o >>= 1) h += __shfl_xor_sync(0xffffffffu, h, o);
    if ((c & 31) == 0) red[c >> 5] = __int_as_float(h);
    __syncthreads();
    if (c == 0) {
        int t = 0;
        #pragma unroll
        for (int i = 0; i < 8; i++) t += __float_as_int(red[i]);
        g_counts[k] = t;
        scnt = max(t, 1);
    }
    __syncthreads();

    float v = g_sums[k * CH + c] / (float)scnt;

    float ss = v * v;
    #pragma unroll
    for (int o = 16; o; o >>= 1) ss += __shfl_xor_sync(0xffffffffu, ss, o);
    if ((c & 31) == 0) red[c >> 5] = ss;
    __syncthreads();
    if (c == 0) {
        float t = 0.0f;
        #pragma unroll
        for (int i = 0; i < 8; i++) t += red[i];
        snorm = fmaxf(sqrtf(t), 1e-12f);
    }
    __syncthreads();
    g_keys[k * CH + c] = v / snorm;
}

// ---------------------------------------------------------------------------
// lse: one block per (k,c) row — 4864 blocks x 128 threads, no inner barriers.
// s = sum_j exp(a*q_j) + exp(a*(qs_j - q_j)) via ex2 (b = a*log2e).
// ---------------------------------------------------------------------------
__global__ void __launch_bounds__(128) lse_kernel(const float* __restrict__ queues,
                                                  float* __restrict__ out_loss) {
    int kc  = blockIdx.x;             // k*CH + c
    int k   = kc >> 8;
    int c   = kc & 255;
    int tid = threadIdx.x;

    float a = g_keys[kc] * INV_T;
    float bb = a * LOG2E;
    const float* rowq  = queues + (size_t)kc * NQ;
    const float* rowqs = g_qsum + (size_t)c * NQ;

    float s0 = 0.0f, s1 = 0.0f;
    #pragma unroll 4
    for (int j = tid; j < NQ; j += 128) {
        float q  = rowq[j];
        float qs = rowqs[j];
        float x  = bb * q;
        s0 += ex2f(x);
        s1 += ex2f(bb * qs - x);
    }
    float s = s0 + s1;

    __shared__ float red[4];
    #pragma unroll
    for (int o = 16; o; o >>= 1) s += __shfl_xor_sync(0xffffffffu, s, o);
    if ((tid & 31) == 0) red[tid >> 5] = s;
    __syncthreads();
    if (tid == 0) {
        float tot = red[0] + red[1] + red[2] + red[3];
        float logit0 = a * rowq[0];
        if (g_counts[k] > 0)
            atomicAdd(out_loss, (__logf(tot) - logit0) * (1.0f / (float)CH));
    }
}

// ---------------------------------------------------------------------------
extern "C" void kernel_launch(void* const* d_in, const int* in_sizes, int n_in,
                              void* d_out, int out_size) {
    const float *fea = nullptr, *res = nullptr, *queues = nullptr;
    for (int i = 0; i < n_in; i++) {
        if (in_sizes[i] == BSZ * CH * HW)        fea    = (const float*)d_in[i];
        else if (in_sizes[i] == BSZ * NCLS * HW) res    = (const float*)d_in[i];
        else if (in_sizes[i] == NCLS * CH * NQ)  queues = (const float*)d_in[i];
    }
    float* out      = (float*)d_out;
    float* out_loss = out + (size_t)BSZ * NCLS * HW;

    pred_kernel<<<PRED_BLOCKS, 256>>>((const float4*)res, (float4*)out, out_loss);
    sums_kernel<<<dim3(CH / CPT, BSZ), 256>>>(fea);
    qsum_keys_kernel<<<QS_BLOCKS + NCLS, 256>>>(queues);
    lse_kernel<<<NCLS * CH, 128>>>(queues, out_loss);
}

// round 10
// speedup vs baseline: 1.5626x; 1.1072x over previous
#include <cuda_runtime.h>

#define NCLS 19
#define CH   256
#define HW   16384      // 128*128
#define HW4  (HW/4)
#define BSZ  8
#define NPIX (BSZ*HW)   // 131072
#define NQ   2975
#define INV_T 5.0f      // 1/0.2
#define LOG2E 1.44269504f

#define PRED_BLOCKS (NPIX/4/256)  // 128
#define KCHUNK 32                 // pixel chunks per batch in sums_mma
#define CHUNK_PIX (HW/KCHUNK)     // 512
#define KSTEPS (CHUNK_PIX/8)      // 64

// ---- device scratch (fully rewritten every launch sequence) ----
__device__ float          g_sums[NCLS*CH];
__device__ int            g_hist[PRED_BLOCKS*NCLS];
__device__ int            g_counts[NCLS];
__device__ float          g_keys[NCLS*CH];
__device__ unsigned char  g_pred[NPIX];

__device__ __forceinline__ float ex2f(float x) {
    float r; asm("ex2.approx.f32 %0, %1;" : "=f"(r) : "f"(x)); return r;
}
__device__ __forceinline__ unsigned cvt_tf32(float x) {
    unsigned r; asm("cvt.rna.tf32.f32 %0, %1;" : "=r"(r) : "f"(x)); return r;
}
// D += A(tf32,row) @ B(tf32,col), m16n8k8
__device__ __forceinline__ void mma_tf32(float* d, const unsigned* a,
                                         unsigned b0, unsigned b1) {
    asm("mma.sync.aligned.m16n8k8.row.col.f32.tf32.tf32.f32 "
        "{%0,%1,%2,%3}, {%4,%5,%6,%7}, {%8,%9}, {%0,%1,%2,%3};"
        : "+f"(d[0]), "+f"(d[1]), "+f"(d[2]), "+f"(d[3])
        : "r"(a[0]), "r"(a[1]), "r"(a[2]), "r"(a[3]), "r"(b0), "r"(b1));
}

// ---------------------------------------------------------------------------
// pred: argmax over classes (x4) + copy res -> out + block hist.
// Also zeroes g_sums and the loss slot.
// ---------------------------------------------------------------------------
__global__ void __launch_bounds__(256) pred_kernel(const float4* __restrict__ res4,
                                                   float4* __restrict__ out4,
                                                   float* __restrict__ out_loss) {
    __shared__ int hist[NCLS];
    int tid = threadIdx.x;
    if (tid < NCLS) hist[tid] = 0;

    int t4 = blockIdx.x * 256 + tid;
    if (t4 < NCLS * CH) g_sums[t4] = 0.0f;
    if (t4 == 0)        *out_loss = 0.0f;
    __syncthreads();

    int b  = t4 >> 12;
    int p4 = t4 & (HW4 - 1);
    const float4* r = res4 + (size_t)b * NCLS * HW4 + p4;
    float4*       o = out4 + (size_t)b * NCLS * HW4 + p4;

    float4 best = r[0];
    o[0] = best;
    int bk0 = 0, bk1 = 0, bk2 = 0, bk3 = 0;
    #pragma unroll
    for (int k = 1; k < NCLS; k++) {
        float4 v = r[(size_t)k * HW4];
        o[(size_t)k * HW4] = v;
        if (v.x > best.x) { best.x = v.x; bk0 = k; }
        if (v.y > best.y) { best.y = v.y; bk1 = k; }
        if (v.z > best.z) { best.z = v.z; bk2 = k; }
        if (v.w > best.w) { best.w = v.w; bk3 = k; }
    }
    ((uchar4*)g_pred)[t4] = make_uchar4((unsigned char)bk0, (unsigned char)bk1,
                                        (unsigned char)bk2, (unsigned char)bk3);
    atomicAdd(&hist[bk0], 1);
    atomicAdd(&hist[bk1], 1);
    atomicAdd(&hist[bk2], 1);
    atomicAdd(&hist[bk3], 1);
    __syncthreads();
    if (tid < NCLS) g_hist[blockIdx.x * NCLS + tid] = hist[tid];
}

// ---------------------------------------------------------------------------
// sums via TF32 tensor cores: sums[k][c] = sum_p onehot[k,p] * fea[c,p].
// A (onehot, row-major [32 x 8]) built in regs from pred; B = fea rows
// (col-major [8 x 8] per n-tile). hi/lo TF32 split keeps fp32 accuracy.
// grid (KCHUNK, BSZ) x 256 thr; warp w owns channels [w*32, w*32+32).
// ---------------------------------------------------------------------------
__global__ void __launch_bounds__(256) sums_mma_kernel(const float* __restrict__ fea) {
    int b     = blockIdx.y;
    int p_base = blockIdx.x * CHUNK_PIX;
    int tid  = threadIdx.x;
    int warp = tid >> 5;
    int lane = tid & 31;
    int gq   = lane >> 2;   // 0..7
    int gr   = lane & 3;    // 0..3
    int c0   = warp * 32;

    __shared__ unsigned char spred[CHUNK_PIX];
    for (int i = tid; i < CHUNK_PIX; i += 256)
        spred[i] = g_pred[b * HW + p_base + i];
    __syncthreads();

    float acc[2][4][4];
    #pragma unroll
    for (int mt = 0; mt < 2; mt++)
        #pragma unroll
        for (int nt = 0; nt < 4; nt++)
            #pragma unroll
            for (int i = 0; i < 4; i++) acc[mt][nt][i] = 0.0f;

    // per n-tile row base: channel = c0 + nt*8 + gq
    const float* base[4];
    #pragma unroll
    for (int nt = 0; nt < 4; nt++)
        base[nt] = fea + (size_t)(b * CH + c0 + nt * 8 + gq) * HW + p_base;

    for (int ks = 0; ks < KSTEPS; ks++) {
        int p = ks * 8;
        int pk0 = spred[p + gr];
        int pk1 = spred[p + gr + 4];

        // A fragments: a0=(row gq, k gr) a1=(row gq+8, k gr)
        //              a2=(row gq, k gr+4) a3=(row gq+8, k gr+4)
        unsigned au[2][4];
        #pragma unroll
        for (int mt = 0; mt < 2; mt++) {
            int cls = mt * 16 + gq;
            au[mt][0] = (pk0 == cls)     ? 0x3f800000u : 0u;
            au[mt][1] = (pk0 == cls + 8) ? 0x3f800000u : 0u;
            au[mt][2] = (pk1 == cls)     ? 0x3f800000u : 0u;
            au[mt][3] = (pk1 == cls + 8) ? 0x3f800000u : 0u;
        }

        #pragma unroll
        for (int nt = 0; nt < 4; nt++) {
            float b0f = base[nt][p + gr];
            float b1f = base[nt][p + gr + 4];
            unsigned b0h = cvt_tf32(b0f);
            unsigned b1h = cvt_tf32(b1f);
            unsigned b0l = cvt_tf32(b0f - __uint_as_float(b0h));
            unsigned b1l = cvt_tf32(b1f - __uint_as_float(b1h));
            #pragma unroll
            for (int mt = 0; mt < 2; mt++) {
                mma_tf32(acc[mt][nt], au[mt], b0h, b1h);
                mma_tf32(acc[mt][nt], au[mt], b0l, b1l);
            }
        }
    }

    // epilogue: D layout d0:(gq, 2gr) d1:(gq, 2gr+1) d2:(gq+8, 2gr) d3:(gq+8, 2gr+1)
    #pragma unroll
    for (int mt = 0; mt < 2; mt++)
        #pragma unroll
        for (int nt = 0; nt < 4; nt++)
            #pragma unroll
            for (int i = 0; i < 4; i++) {
                int cls = mt * 16 + gq + ((i >> 1) << 3);
                if (cls < NCLS) {
                    int ch = c0 + nt * 8 + 2 * gr + (i & 1);
                    atomicAdd(&g_sums[cls * CH + ch], acc[mt][nt][i]);
                }
            }
}

// ---------------------------------------------------------------------------
// keys: hist->counts, masked mean + L2 normalize along C. One block per class.
// ---------------------------------------------------------------------------
__global__ void __launch_bounds__(256) keys_kernel() {
    int k = blockIdx.x;
    int c = threadIdx.x;

    __shared__ float red[8];
    __shared__ float snorm;
    __shared__ int   scnt;

    int h = 0;
    for (int pb = c; pb < PRED_BLOCKS; pb += 256) h += g_hist[pb * NCLS + k];
    #pragma unroll
    for (int o = 16; o; o >>= 1) h += __shfl_xor_sync(0xffffffffu, h, o);
    if ((c & 31) == 0) red[c >> 5] = __int_as_float(h);
    __syncthreads();
    if (c == 0) {
        int t = 0;
        #pragma unroll
        for (int i = 0; i < 8; i++) t += __float_as_int(red[i]);
        g_counts[k] = t;
        scnt = max(t, 1);
    }
    __syncthreads();

    float v = g_sums[k * CH + c] / (float)scnt;

    float ss = v * v;
    #pragma unroll
    for (int o = 16; o; o >>= 1) ss += __shfl_xor_sync(0xffffffffu, ss, o);
    if ((c & 31) == 0) red[c >> 5] = ss;
    __syncthreads();
    if (c == 0) {
        float t = 0.0f;
        #pragma unroll
        for (int i = 0; i < 8; i++) t += red[i];
        snorm = fmaxf(sqrtf(t), 1e-12f);
    }
    __syncthreads();
    g_keys[k * CH + c] = v / snorm;
}

// ---------------------------------------------------------------------------
// lse one-pass: one block per channel c. For each j, load the 19-class
// column of queues once, build qsum inline, accumulate all 19 LSE sums in
// registers. queues is read exactly once chip-wide; no qsum buffer.
// ---------------------------------------------------------------------------
__global__ void __launch_bounds__(256) lse_kernel(const float* __restrict__ queues,
                                                  float* __restrict__ out_loss) {
    int c   = blockIdx.x;
    int tid = threadIdx.x;

    __shared__ float sbb[NCLS];   // a_k * log2e
    __shared__ float sl0[NCLS];   // logit0_k = a_k * q_k0
    if (tid < NCLS) {
        float a = g_keys[tid * CH + c] * INV_T;
        sbb[tid] = a * LOG2E;
        sl0[tid] = a * queues[((size_t)(tid * CH + c)) * NQ];
    }
    __syncthreads();

    float bb[NCLS];
    #pragma unroll
    for (int k = 0; k < NCLS; k++) bb[k] = sbb[k];

    const float* base = queues + (size_t)c * NQ;
    float s[NCLS];
    #pragma unroll
    for (int k = 0; k < NCLS; k++) s[k] = 0.0f;

    for (int j = tid; j < NQ; j += 256) {
        float q[NCLS];
        float qs = 0.0f;
        #pragma unroll
        for (int k = 0; k < NCLS; k++) {
            q[k] = base[(size_t)k * CH * NQ + j];
            qs += q[k];
        }
        #pragma unroll
        for (int k = 0; k < NCLS; k++) {
            float x = bb[k] * q[k];
            s[k] += ex2f(x) + ex2f(bb[k] * qs - x);
        }
    }

    // block reduce all 19 sums
    __shared__ float wred[8][NCLS];
    int lane = tid & 31, wid = tid >> 5;
    #pragma unroll
    for (int k = 0; k < NCLS; k++) {
        float v = s[k];
        #pragma unroll
        for (int o = 16; o; o >>= 1) v += __shfl_xor_sync(0xffffffffu, v, o);
        if (lane == 0) wred[wid][k] = v;
    }
    __syncthreads();

    if (tid < 32) {
        float part = 0.0f;
        if (tid < NCLS && g_counts[tid] > 0) {
            float tot = 0.0f;
            #pragma unroll
            for (int w = 0; w < 8; w++) tot += wred[w][tid];
            part = (__logf(tot) - sl0[tid]) * (1.0f / (float)CH);
        }
        #pragma unroll
        for (int o = 16; o; o >>= 1) part += __shfl_xor_sync(0xffffffffu, part, o);
        if (tid == 0) atomicAdd(out_loss, part);
    }
}

// ---------------------------------------------------------------------------
extern "C" void kernel_launch(void* const* d_in, const int* in_sizes, int n_in,
                              void* d_out, int out_size) {
    const float *fea = nullptr, *res = nullptr, *queues = nullptr;
    for (int i = 0; i < n_in; i++) {
        if (in_sizes[i] == BSZ * CH * HW)        fea    = (const float*)d_in[i];
        else if (in_sizes[i] == BSZ * NCLS * HW) res    = (const float*)d_in[i];
        else if (in_sizes[i] == NCLS * CH * NQ)  queues = (const float*)d_in[i];
    }
    float* out      = (float*)d_out;
    float* out_loss = out + (size_t)BSZ * NCLS * HW;

    pred_kernel<<<PRED_BLOCKS, 256>>>((const float4*)res, (float4*)out, out_loss);
    sums_mma_kernel<<<dim3(KCHUNK, BSZ), 256>>>(fea);
    keys_kernel<<<NCLS, 256>>>();
    lse_kernel<<<CH, 256>>>(queues, out_loss);
}

// round 11
// speedup vs baseline: 1.5647x; 1.0014x over previous
#include <cuda_runtime.h>

#define NCLS 19
#define CH   256
#define HW   16384      // 128*128
#define HW4  (HW/4)
#define BSZ  8
#define NPIX (BSZ*HW)   // 131072
#define NQ   2975
#define INV_T 5.0f      // 1/0.2
#define LOG2E 1.44269504f

#define PRED_BLOCKS (NPIX/4/256)  // 128
#define KCHUNK 64                 // pixel chunks per batch in sums_mma
#define CHUNK_PIX (HW/KCHUNK)     // 256
#define KSTEPS (CHUNK_PIX/8)      // 32

#define LSE_THREADS 512

// ---- device scratch (fully rewritten every launch sequence) ----
__device__ float          g_sums[NCLS*CH];
__device__ int            g_hist[PRED_BLOCKS*NCLS];
__device__ int            g_counts[NCLS];
__device__ float          g_keys[NCLS*CH];
__device__ unsigned char  g_pred[NPIX];

__device__ __forceinline__ float ex2f(float x) {
    float r; asm("ex2.approx.f32 %0, %1;" : "=f"(r) : "f"(x)); return r;
}
__device__ __forceinline__ unsigned cvt_tf32(float x) {
    unsigned r; asm("cvt.rna.tf32.f32 %0, %1;" : "=r"(r) : "f"(x)); return r;
}
// D += A(tf32,row) @ B(tf32,col), m16n8k8
__device__ __forceinline__ void mma_tf32(float* d, const unsigned* a,
                                         unsigned b0, unsigned b1) {
    asm("mma.sync.aligned.m16n8k8.row.col.f32.tf32.tf32.f32 "
        "{%0,%1,%2,%3}, {%4,%5,%6,%7}, {%8,%9}, {%0,%1,%2,%3};"
        : "+f"(d[0]), "+f"(d[1]), "+f"(d[2]), "+f"(d[3])
        : "r"(a[0]), "r"(a[1]), "r"(a[2]), "r"(a[3]), "r"(b0), "r"(b1));
}

// ---------------------------------------------------------------------------
// pred: argmax over classes (x4) + copy res -> out + block hist.
// Also zeroes g_sums and the loss slot.
// ---------------------------------------------------------------------------
__global__ void __launch_bounds__(256) pred_kernel(const float4* __restrict__ res4,
                                                   float4* __restrict__ out4,
                                                   float* __restrict__ out_loss) {
    __shared__ int hist[NCLS];
    int tid = threadIdx.x;
    if (tid < NCLS) hist[tid] = 0;

    int t4 = blockIdx.x * 256 + tid;
    if (t4 < NCLS * CH) g_sums[t4] = 0.0f;
    if (t4 == 0)        *out_loss = 0.0f;
    __syncthreads();

    int b  = t4 >> 12;
    int p4 = t4 & (HW4 - 1);
    const float4* r = res4 + (size_t)b * NCLS * HW4 + p4;
    float4*       o = out4 + (size_t)b * NCLS * HW4 + p4;

    float4 best = r[0];
    o[0] = best;
    int bk0 = 0, bk1 = 0, bk2 = 0, bk3 = 0;
    #pragma unroll
    for (int k = 1; k < NCLS; k++) {
        float4 v = r[(size_t)k * HW4];
        o[(size_t)k * HW4] = v;
        if (v.x > best.x) { best.x = v.x; bk0 = k; }
        if (v.y > best.y) { best.y = v.y; bk1 = k; }
        if (v.z > best.z) { best.z = v.z; bk2 = k; }
        if (v.w > best.w) { best.w = v.w; bk3 = k; }
    }
    ((uchar4*)g_pred)[t4] = make_uchar4((unsigned char)bk0, (unsigned char)bk1,
                                        (unsigned char)bk2, (unsigned char)bk3);
    atomicAdd(&hist[bk0], 1);
    atomicAdd(&hist[bk1], 1);
    atomicAdd(&hist[bk2], 1);
    atomicAdd(&hist[bk3], 1);
    __syncthreads();
    if (tid < NCLS) g_hist[blockIdx.x * NCLS + tid] = hist[tid];
}

// ---------------------------------------------------------------------------
// sums via TF32 tensor cores: sums[k][c] = sum_p onehot[k,p] * fea[c,p].
// grid (KCHUNK, BSZ) = 512 blocks (latency hiding via block count).
// ---------------------------------------------------------------------------
__global__ void __launch_bounds__(256) sums_mma_kernel(const float* __restrict__ fea) {
    int b      = blockIdx.y;
    int p_base = blockIdx.x * CHUNK_PIX;
    int tid  = threadIdx.x;
    int warp = tid >> 5;
    int lane = tid & 31;
    int gq   = lane >> 2;   // 0..7
    int gr   = lane & 3;    // 0..3
    int c0   = warp * 32;

    __shared__ unsigned char spred[CHUNK_PIX];
    for (int i = tid; i < CHUNK_PIX; i += 256)
        spred[i] = g_pred[b * HW + p_base + i];
    __syncthreads();

    float acc[2][4][4];
    #pragma unroll
    for (int mt = 0; mt < 2; mt++)
        #pragma unroll
        for (int nt = 0; nt < 4; nt++)
            #pragma unroll
            for (int i = 0; i < 4; i++) acc[mt][nt][i] = 0.0f;

    const float* base[4];
    #pragma unroll
    for (int nt = 0; nt < 4; nt++)
        base[nt] = fea + (size_t)(b * CH + c0 + nt * 8 + gq) * HW + p_base;

    for (int ks = 0; ks < KSTEPS; ks++) {
        int p = ks * 8;
        int pk0 = spred[p + gr];
        int pk1 = spred[p + gr + 4];

        unsigned au[2][4];
        #pragma unroll
        for (int mt = 0; mt < 2; mt++) {
            int cls = mt * 16 + gq;
            au[mt][0] = (pk0 == cls)     ? 0x3f800000u : 0u;
            au[mt][1] = (pk0 == cls + 8) ? 0x3f800000u : 0u;
            au[mt][2] = (pk1 == cls)     ? 0x3f800000u : 0u;
            au[mt][3] = (pk1 == cls + 8) ? 0x3f800000u : 0u;
        }

        // issue all 8 loads up front (MLP), then convert + mma
        float b0f[4], b1f[4];
        #pragma unroll
        for (int nt = 0; nt < 4; nt++) {
            b0f[nt] = base[nt][p + gr];
            b1f[nt] = base[nt][p + gr + 4];
        }

        #pragma unroll
        for (int nt = 0; nt < 4; nt++) {
            unsigned b0h = cvt_tf32(b0f[nt]);
            unsigned b1h = cvt_tf32(b1f[nt]);
            unsigned b0l = cvt_tf32(b0f[nt] - __uint_as_float(b0h));
            unsigned b1l = cvt_tf32(b1f[nt] - __uint_as_float(b1h));
            #pragma unroll
            for (int mt = 0; mt < 2; mt++) {
                mma_tf32(acc[mt][nt], au[mt], b0h, b1h);
                mma_tf32(acc[mt][nt], au[mt], b0l, b1l);
            }
        }
    }

    // epilogue: D layout d0:(gq, 2gr) d1:(gq, 2gr+1) d2:(gq+8, 2gr) d3:(gq+8, 2gr+1)
    #pragma unroll
    for (int mt = 0; mt < 2; mt++)
        #pragma unroll
        for (int nt = 0; nt < 4; nt++)
            #pragma unroll
            for (int i = 0; i < 4; i++) {
                int cls = mt * 16 + gq + ((i >> 1) << 3);
                if (cls < NCLS) {
                    int ch = c0 + nt * 8 + 2 * gr + (i & 1);
                    atomicAdd(&g_sums[cls * CH + ch], acc[mt][nt][i]);
                }
            }
}

// ---------------------------------------------------------------------------
// keys: hist->counts, masked mean + L2 normalize along C. One block per class.
// ---------------------------------------------------------------------------
__global__ void __launch_bounds__(256) keys_kernel() {
    int k = blockIdx.x;
    int c = threadIdx.x;

    __shared__ float red[8];
    __shared__ float snorm;
    __shared__ int   scnt;

    int h = 0;
    for (int pb = c; pb < PRED_BLOCKS; pb += 256) h += g_hist[pb * NCLS + k];
    #pragma unroll
    for (int o = 16; o; o >>= 1) h += __shfl_xor_sync(0xffffffffu, h, o);
    if ((c & 31) == 0) red[c >> 5] = __int_as_float(h);
    __syncthreads();
    if (c == 0) {
        int t = 0;
        #pragma unroll
        for (int i = 0; i < 8; i++) t += __float_as_int(red[i]);
        g_counts[k] = t;
        scnt = max(t, 1);
    }
    __syncthreads();

    float v = g_sums[k * CH + c] / (float)scnt;

    float ss = v * v;
    #pragma unroll
    for (int o = 16; o; o >>= 1) ss += __shfl_xor_sync(0xffffffffu, ss, o);
    if ((c & 31) == 0) red[c >> 5] = ss;
    __syncthreads();
    if (c == 0) {
        float t = 0.0f;
        #pragma unroll
        for (int i = 0; i < 8; i++) t += red[i];
        snorm = fmaxf(sqrtf(t), 1e-12f);
    }
    __syncthreads();
    g_keys[k * CH + c] = v / snorm;
}

// ---------------------------------------------------------------------------
// lse one-pass: one block (512 thr) per channel c. For each j, load the
// 19-class column of queues once, build qsum inline, accumulate all 19 LSE
// sums in registers. queues read exactly once chip-wide.
// ---------------------------------------------------------------------------
__global__ void __launch_bounds__(LSE_THREADS) lse_kernel(const float* __restrict__ queues,
                                                          float* __restrict__ out_loss) {
    int c   = blockIdx.x;
    int tid = threadIdx.x;

    __shared__ float sbb[NCLS];   // a_k * log2e
    __shared__ float sl0[NCLS];   // logit0_k = a_k * q_k0
    if (tid < NCLS) {
        float a = g_keys[tid * CH + c] * INV_T;
        sbb[tid] = a * LOG2E;
        sl0[tid] = a * queues[((size_t)(tid * CH + c)) * NQ];
    }
    __syncthreads();

    float bb[NCLS];
    #pragma unroll
    for (int k = 0; k < NCLS; k++) bb[k] = sbb[k];

    const float* base = queues + (size_t)c * NQ;
    float s[NCLS];
    #pragma unroll
    for (int k = 0; k < NCLS; k++) s[k] = 0.0f;

    for (int j = tid; j < NQ; j += LSE_THREADS) {
        float q[NCLS];
        float qs = 0.0f;
        #pragma unroll
        for (int k = 0; k < NCLS; k++) {
            q[k] = base[(size_t)k * CH * NQ + j];
            qs += q[k];
        }
        #pragma unroll
        for (int k = 0; k < NCLS; k++) {
            float x = bb[k] * q[k];
            s[k] += ex2f(x) + ex2f(bb[k] * qs - x);
        }
    }

    // block reduce all 19 sums
    __shared__ float wred[LSE_THREADS / 32][NCLS];
    int lane = tid & 31, wid = tid >> 5;
    #pragma unroll
    for (int k = 0; k < NCLS; k++) {
        float v = s[k];
        #pragma unroll
        for (int o = 16; o; o >>= 1) v += __shfl_xor_sync(0xffffffffu, v, o);
        if (lane == 0) wred[wid][k] = v;
    }
    __syncthreads();

    if (tid < 32) {
        float part = 0.0f;
        if (tid < NCLS && g_counts[tid] > 0) {
            float tot = 0.0f;
            #pragma unroll
            for (int w = 0; w < LSE_THREADS / 32; w++) tot += wred[w][tid];
            part = (__logf(tot) - sl0[tid]) * (1.0f / (float)CH);
        }
        #pragma unroll
        for (int o = 16; o; o >>= 1) part += __shfl_xor_sync(0xffffffffu, part, o);
        if (tid == 0) atomicAdd(out_loss, part);
    }
}

// ---------------------------------------------------------------------------
extern "C" void kernel_launch(void* const* d_in, const int* in_sizes, int n_in,
                              void* d_out, int out_size) {
    const float *fea = nullptr, *res = nullptr, *queues = nullptr;
    for (int i = 0; i < n_in; i++) {
        if (in_sizes[i] == BSZ * CH * HW)        fea    = (const float*)d_in[i];
        else if (in_sizes[i] == BSZ * NCLS * HW) res    = (const float*)d_in[i];
        else if (in_sizes[i] == NCLS * CH * NQ)  queues = (const float*)d_in[i];
    }
    float* out      = (float*)d_out;
    float* out_loss = out + (size_t)BSZ * NCLS * HW;

    pred_kernel<<<PRED_BLOCKS, 256>>>((const float4*)res, (float4*)out, out_loss);
    sums_mma_kernel<<<dim3(KCHUNK, BSZ), 256>>>(fea);
    keys_kernel<<<NCLS, 256>>>();
    lse_kernel<<<CH, LSE_THREADS>>>(queues, out_loss);
}

// round 12
// speedup vs baseline: 1.6744x; 1.0701x over previous
#include <cuda_runtime.h>

#define NCLS 19
#define CH   256
#define HW   16384      // 128*128
#define BSZ  8
#define NQ   2975
#define INV_T 5.0f      // 1/0.2
#define LOG2E 1.44269504f

#define KCHUNK 64                 // pixel chunks per batch
#define CHUNK_PIX (HW/KCHUNK)     // 256
#define KSTEPS (CHUNK_PIX/8)      // 32
#define SUMS_BLOCKS (KCHUNK*BSZ)  // 512
#define NHALF 1488                // ceil(NQ/2)

// ---- device scratch. Protocol (all kernel-boundary ordered, no tickets):
//  g_sums: zero at load; fused atomicAdds; keys reads; lse re-zeros.
//  g_lse : zero at load; lse atomicAdds; finalize reads then re-zeros.
//  out_loss: fused zeroes at replay start; finalize atomicAdds.
//  g_hist/g_counts/g_keys: overwrite semantics.
__device__ float g_sums[NCLS*CH];
__device__ float g_lse[NCLS*CH];
__device__ int   g_hist[SUMS_BLOCKS*NCLS];
__device__ int   g_counts[NCLS];
__device__ float g_keys[NCLS*CH];

__device__ __forceinline__ float ex2f(float x) {
    float r; asm("ex2.approx.f32 %0, %1;" : "=f"(r) : "f"(x)); return r;
}
__device__ __forceinline__ unsigned cvt_tf32(float x) {
    unsigned r; asm("cvt.rna.tf32.f32 %0, %1;" : "=r"(r) : "f"(x)); return r;
}
__device__ __forceinline__ void mma_tf32(float* d, const unsigned* a,
                                         unsigned b0, unsigned b1) {
    asm("mma.sync.aligned.m16n8k8.row.col.f32.tf32.tf32.f32 "
        "{%0,%1,%2,%3}, {%4,%5,%6,%7}, {%8,%9}, {%0,%1,%2,%3};"
        : "+f"(d[0]), "+f"(d[1]), "+f"(d[2]), "+f"(d[3])
        : "r"(a[0]), "r"(a[1]), "r"(a[2]), "r"(a[3]), "r"(b0), "r"(b1));
}

// ---------------------------------------------------------------------------
// fused pred + sums: block (chunk, b) owns 256 pixels x all 256 channels.
// Phase 1: per-pixel argmax over res (coalesced per class), res->out copy,
//          block hist -> g_hist.  Phase 2: TF32 MMA masked pooling of fea.
// ---------------------------------------------------------------------------
__global__ void __launch_bounds__(256) fused_kernel(const float* __restrict__ res,
                                                    float* __restrict__ out,
                                                    const float* __restrict__ fea,
                                                    float* __restrict__ out_loss) {
    int b      = blockIdx.y;
    int chunk  = blockIdx.x;
    int p_base = chunk * CHUNK_PIX;
    int tid  = threadIdx.x;

    __shared__ unsigned char spred[CHUNK_PIX];
    __shared__ int hist[NCLS];
    if (tid < NCLS) hist[tid] = 0;
    if (b == 0 && chunk == 0 && tid == 0) *out_loss = 0.0f;
    __syncthreads();

    // ---- phase 1: pred for pixel p_base + tid ----
    {
        const float* r = res + (size_t)b * NCLS * HW + p_base + tid;
        float*       o = out + (size_t)b * NCLS * HW + p_base + tid;
        float best = r[0];
        o[0] = best;
        int bk = 0;
        #pragma unroll
        for (int k = 1; k < NCLS; k++) {
            float v = r[(size_t)k * HW];
            o[(size_t)k * HW] = v;
            if (v > best) { best = v; bk = k; }
        }
        spred[tid] = (unsigned char)bk;
        atomicAdd(&hist[bk], 1);
    }
    __syncthreads();
    if (tid < NCLS) g_hist[(b * KCHUNK + chunk) * NCLS + tid] = hist[tid];

    // ---- phase 2: TF32 MMA pooling ----
    int warp = tid >> 5;
    int lane = tid & 31;
    int gq   = lane >> 2;
    int gr   = lane & 3;
    int c0   = warp * 32;

    float acc[2][4][4];
    #pragma unroll
    for (int mt = 0; mt < 2; mt++)
        #pragma unroll
        for (int nt = 0; nt < 4; nt++)
            #pragma unroll
            for (int i = 0; i < 4; i++) acc[mt][nt][i] = 0.0f;

    const float* base[4];
    #pragma unroll
    for (int nt = 0; nt < 4; nt++)
        base[nt] = fea + (size_t)(b * CH + c0 + nt * 8 + gq) * HW + p_base;

    for (int ks = 0; ks < KSTEPS; ks++) {
        int p = ks * 8;
        int pk0 = spred[p + gr];
        int pk1 = spred[p + gr + 4];

        unsigned au[2][4];
        #pragma unroll
        for (int mt = 0; mt < 2; mt++) {
            int cls = mt * 16 + gq;
            au[mt][0] = (pk0 == cls)     ? 0x3f800000u : 0u;
            au[mt][1] = (pk0 == cls + 8) ? 0x3f800000u : 0u;
            au[mt][2] = (pk1 == cls)     ? 0x3f800000u : 0u;
            au[mt][3] = (pk1 == cls + 8) ? 0x3f800000u : 0u;
        }

        float b0f[4], b1f[4];
        #pragma unroll
        for (int nt = 0; nt < 4; nt++) {
            b0f[nt] = base[nt][p + gr];
            b1f[nt] = base[nt][p + gr + 4];
        }

        #pragma unroll
        for (int nt = 0; nt < 4; nt++) {
            unsigned b0h = cvt_tf32(b0f[nt]);
            unsigned b1h = cvt_tf32(b1f[nt]);
            unsigned b0l = cvt_tf32(b0f[nt] - __uint_as_float(b0h));
            unsigned b1l = cvt_tf32(b1f[nt] - __uint_as_float(b1h));
            #pragma unroll
            for (int mt = 0; mt < 2; mt++) {
                mma_tf32(acc[mt][nt], au[mt], b0h, b1h);
                mma_tf32(acc[mt][nt], au[mt], b0l, b1l);
            }
        }
    }

    #pragma unroll
    for (int mt = 0; mt < 2; mt++)
        #pragma unroll
        for (int nt = 0; nt < 4; nt++)
            #pragma unroll
            for (int i = 0; i < 4; i++) {
                int cls = mt * 16 + gq + ((i >> 1) << 3);
                if (cls < NCLS) {
                    int ch = c0 + nt * 8 + 2 * gr + (i & 1);
                    atomicAdd(&g_sums[cls * CH + ch], acc[mt][nt][i]);
                }
            }
}

// ---------------------------------------------------------------------------
// keys: hist->counts, masked mean + L2 normalize. One block per class.
// ---------------------------------------------------------------------------
__global__ void __launch_bounds__(256) keys_kernel() {
    int k = blockIdx.x;
    int c = threadIdx.x;

    __shared__ float red[8];
    __shared__ float snorm;
    __shared__ int   scnt;

    int h = 0;
    for (int i = c; i < SUMS_BLOCKS; i += 256) h += g_hist[i * NCLS + k];
    #pragma unroll
    for (int o = 16; o; o >>= 1) h += __shfl_xor_sync(0xffffffffu, h, o);
    if ((c & 31) == 0) red[c >> 5] = __int_as_float(h);
    __syncthreads();
    if (c == 0) {
        int t = 0;
        #pragma unroll
        for (int i = 0; i < 8; i++) t += __float_as_int(red[i]);
        g_counts[k] = t;
        scnt = max(t, 1);
    }
    __syncthreads();

    float v = g_sums[k * CH + c] / (float)scnt;

    float ss = v * v;
    #pragma unroll
    for (int o = 16; o; o >>= 1) ss += __shfl_xor_sync(0xffffffffu, ss, o);
    if ((c & 31) == 0) red[c >> 5] = ss;
    __syncthreads();
    if (c == 0) {
        float t = 0.0f;
        #pragma unroll
        for (int i = 0; i < 8; i++) t += red[i];
        snorm = fmaxf(sqrtf(t), 1e-12f);
    }
    __syncthreads();
    g_keys[k * CH + c] = v / snorm;
}

// ---------------------------------------------------------------------------
// lse partial: grid (CH, 2), 256 thr. Block (c, half) handles its j-range,
// reads the 19-class column once, builds qsum inline, accumulates 19 exp-sums
// and atomicAdds them into g_lse. Blocks (c<19, half=0) also re-zero g_sums
// for the next replay (keys already consumed it this replay).
// ---------------------------------------------------------------------------
__global__ void __launch_bounds__(256) lse_kernel(const float* __restrict__ queues) {
    int c    = blockIdx.x;
    int half = blockIdx.y;
    int tid  = threadIdx.x;

    if (half == 0 && c < NCLS) g_sums[c * CH + tid] = 0.0f;

    __shared__ float sbb[NCLS];
    if (tid < NCLS) sbb[tid] = g_keys[tid * CH + c] * (INV_T * LOG2E);
    __syncthreads();

    float bb[NCLS];
    #pragma unroll
    for (int k = 0; k < NCLS; k++) bb[k] = sbb[k];

    const float* base = queues + (size_t)c * NQ;
    float s[NCLS];
    #pragma unroll
    for (int k = 0; k < NCLS; k++) s[k] = 0.0f;

    int jend = min(NQ, (half + 1) * NHALF);
    for (int j = half * NHALF + tid; j < jend; j += 256) {
        float q[NCLS];
        float qs = 0.0f;
        #pragma unroll
        for (int k = 0; k < NCLS; k++) {
            q[k] = base[(size_t)k * CH * NQ + j];
            qs += q[k];
        }
        #pragma unroll
        for (int k = 0; k < NCLS; k++) {
            float x = bb[k] * q[k];
            s[k] += ex2f(x) + ex2f(bb[k] * qs - x);
        }
    }

    __shared__ float wred[8][NCLS];
    int lane = tid & 31, wid = tid >> 5;
    #pragma unroll
    for (int k = 0; k < NCLS; k++) {
        float v = s[k];
        #pragma unroll
        for (int o = 16; o; o >>= 1) v += __shfl_xor_sync(0xffffffffu, v, o);
        if (lane == 0) wred[wid][k] = v;
    }
    __syncthreads();
    if (tid < NCLS) {
        float tot = 0.0f;
        #pragma unroll
        for (int w = 0; w < 8; w++) tot += wred[w][tid];
        atomicAdd(&g_lse[tid * CH + c], tot);
    }
}

// ---------------------------------------------------------------------------
// finalize: 19 blocks x 256 thr. loss_kc = (log(tot) - a*q0)/CH, gated by
// counts; block-reduce; atomicAdd to out_loss. Re-zeros g_lse after reading.
// ---------------------------------------------------------------------------
__global__ void __launch_bounds__(256) finalize_kernel(const float* __restrict__ queues,
                                                       float* __restrict__ out_loss) {
    int k = blockIdx.x;
    int c = threadIdx.x;

    float tot = g_lse[k * CH + c];
    g_lse[k * CH + c] = 0.0f;

    float part = 0.0f;
    if (g_counts[k] > 0) {
        float a  = g_keys[k * CH + c] * INV_T;
        float q0 = queues[((size_t)(k * CH + c)) * NQ];
        part = (__logf(tot) - a * q0) * (1.0f / (float)CH);
    }

    __shared__ float red[8];
    #pragma unroll
    for (int o = 16; o; o >>= 1) part += __shfl_xor_sync(0xffffffffu, part, o);
    if ((c & 31) == 0) red[c >> 5] = part;
    __syncthreads();
    if (c == 0) {
        float t = 0.0f;
        #pragma unroll
        for (int i = 0; i < 8; i++) t += red[i];
        atomicAdd(out_loss, t);
    }
}

// ---------------------------------------------------------------------------
extern "C" void kernel_launch(void* const* d_in, const int* in_sizes, int n_in,
                              void* d_out, int out_size) {
    const float *fea = nullptr, *res = nullptr, *queues = nullptr;
    for (int i = 0; i < n_in; i++) {
        if (in_sizes[i] == BSZ * CH * HW)        fea    = (const float*)d_in[i];
        else if (in_sizes[i] == BSZ * NCLS * HW) res    = (const float*)d_in[i];
        else if (in_sizes[i] == NCLS * CH * NQ)  queues = (const float*)d_in[i];
    }
    float* out      = (float*)d_out;
    float* out_loss = out + (size_t)BSZ * NCLS * HW;

    fused_kernel<<<dim3(KCHUNK, BSZ), 256>>>(res, out, fea, out_loss);
    keys_kernel<<<NCLS, 256>>>();
    lse_kernel<<<dim3(CH, 2), 256>>>(queues);
    finalize_kernel<<<NCLS, 256>>>(queues, out_loss);
}

// round 13
// speedup vs baseline: 1.8462x; 1.1026x over previous
#include <cuda_runtime.h>

#define NCLS 19
#define CH   256
#define HW   16384      // 128*128
#define BSZ  8
#define NQ   2975
#define INV_T 5.0f      // 1/0.2
#define LOG2E 1.44269504f

#define KCHUNK 64                 // pixel chunks per batch
#define CHUNK_PIX (HW/KCHUNK)     // 256
#define KSTEPS (CHUNK_PIX/8)      // 32
#define SUMS_BLOCKS (KCHUNK*BSZ)  // 512
#define NHALF 1488                // ceil(NQ/2)

// ---- device scratch. Protocol (kernel-boundary ordered, no tickets):
//  g_sums: zero at load; fused atomicAdds; keys reads; lse re-zeros.
//  g_lse : zero at load; lse atomicAdds; second-arriver reads+resets.
//  out_loss: keys zeroes; lse completers atomicAdd.
//  g_hist/g_counts/g_keys: overwrite semantics.
__device__ float g_sums[NCLS*CH];
__device__ float g_lse[NCLS*CH];
__device__ int   g_hist[SUMS_BLOCKS*NCLS];
__device__ int   g_counts[NCLS];
__device__ float g_keys[NCLS*CH];

__device__ __forceinline__ float ex2f(float x) {
    float r; asm("ex2.approx.f32 %0, %1;" : "=f"(r) : "f"(x)); return r;
}
__device__ __forceinline__ unsigned cvt_tf32(float x) {
    unsigned r; asm("cvt.rna.tf32.f32 %0, %1;" : "=r"(r) : "f"(x)); return r;
}
__device__ __forceinline__ void mma_tf32(float* d, const unsigned* a,
                                         unsigned b0, unsigned b1) {
    asm("mma.sync.aligned.m16n8k8.row.col.f32.tf32.tf32.f32 "
        "{%0,%1,%2,%3}, {%4,%5,%6,%7}, {%8,%9}, {%0,%1,%2,%3};"
        : "+f"(d[0]), "+f"(d[1]), "+f"(d[2]), "+f"(d[3])
        : "r"(a[0]), "r"(a[1]), "r"(a[2]), "r"(a[3]), "r"(b0), "r"(b1));
}

// ---------------------------------------------------------------------------
// fused pred + sums: block (chunk, b) owns 256 pixels x all 256 channels.
// Phase 1: per-pixel argmax over res + res->out copy + block hist.
// Phase 2: TF32 MMA masked pooling of fea, software-pipelined loads.
// ---------------------------------------------------------------------------
__global__ void __launch_bounds__(256) fused_kernel(const float* __restrict__ res,
                                                    float* __restrict__ out,
                                                    const float* __restrict__ fea) {
    int b      = blockIdx.y;
    int chunk  = blockIdx.x;
    int p_base = chunk * CHUNK_PIX;
    int tid  = threadIdx.x;

    __shared__ unsigned char spred[CHUNK_PIX];
    __shared__ int hist[NCLS];
    if (tid < NCLS) hist[tid] = 0;
    __syncthreads();

    // ---- phase 1: pred for pixel p_base + tid ----
    {
        const float* r = res + (size_t)b * NCLS * HW + p_base + tid;
        float*       o = out + (size_t)b * NCLS * HW + p_base + tid;
        float best = r[0];
        o[0] = best;
        int bk = 0;
        #pragma unroll
        for (int k = 1; k < NCLS; k++) {
            float v = r[(size_t)k * HW];
            o[(size_t)k * HW] = v;
            if (v > best) { best = v; bk = k; }
        }
        spred[tid] = (unsigned char)bk;
        atomicAdd(&hist[bk], 1);
    }
    __syncthreads();
    if (tid < NCLS) g_hist[(b * KCHUNK + chunk) * NCLS + tid] = hist[tid];

    // ---- phase 2: TF32 MMA pooling (pipelined) ----
    int warp = tid >> 5;
    int lane = tid & 31;
    int gq   = lane >> 2;
    int gr   = lane & 3;
    int c0   = warp * 32;

    float acc[2][4][4];
    #pragma unroll
    for (int mt = 0; mt < 2; mt++)
        #pragma unroll
        for (int nt = 0; nt < 4; nt++)
            #pragma unroll
            for (int i = 0; i < 4; i++) acc[mt][nt][i] = 0.0f;

    const float* base[4];
    #pragma unroll
    for (int nt = 0; nt < 4; nt++)
        base[nt] = fea + (size_t)(b * CH + c0 + nt * 8 + gq) * HW + p_base;

    // prologue loads for ks = 0
    float b0f[4], b1f[4];
    #pragma unroll
    for (int nt = 0; nt < 4; nt++) {
        b0f[nt] = base[nt][gr];
        b1f[nt] = base[nt][gr + 4];
    }

    for (int ks = 0; ks < KSTEPS; ks++) {
        int p = ks * 8;
        int pk0 = spred[p + gr];
        int pk1 = spred[p + gr + 4];

        // stash current batch, then issue next iteration's loads
        float c0f[4], c1f[4];
        #pragma unroll
        for (int nt = 0; nt < 4; nt++) { c0f[nt] = b0f[nt]; c1f[nt] = b1f[nt]; }
        if (ks + 1 < KSTEPS) {
            int pn = p + 8;
            #pragma unroll
            for (int nt = 0; nt < 4; nt++) {
                b0f[nt] = base[nt][pn + gr];
                b1f[nt] = base[nt][pn + gr + 4];
            }
        }

        unsigned au[2][4];
        #pragma unroll
        for (int mt = 0; mt < 2; mt++) {
            int cls = mt * 16 + gq;
            au[mt][0] = (pk0 == cls)     ? 0x3f800000u : 0u;
            au[mt][1] = (pk0 == cls + 8) ? 0x3f800000u : 0u;
            au[mt][2] = (pk1 == cls)     ? 0x3f800000u : 0u;
            au[mt][3] = (pk1 == cls + 8) ? 0x3f800000u : 0u;
        }

        #pragma unroll
        for (int nt = 0; nt < 4; nt++) {
            unsigned b0h = cvt_tf32(c0f[nt]);
            unsigned b1h = cvt_tf32(c1f[nt]);
            unsigned b0l = cvt_tf32(c0f[nt] - __uint_as_float(b0h));
            unsigned b1l = cvt_tf32(c1f[nt] - __uint_as_float(b1h));
            #pragma unroll
            for (int mt = 0; mt < 2; mt++) {
                mma_tf32(acc[mt][nt], au[mt], b0h, b1h);
                mma_tf32(acc[mt][nt], au[mt], b0l, b1l);
            }
        }
    }

    #pragma unroll
    for (int mt = 0; mt < 2; mt++)
        #pragma unroll
        for (int nt = 0; nt < 4; nt++)
            #pragma unroll
            for (int i = 0; i < 4; i++) {
                int cls = mt * 16 + gq + ((i >> 1) << 3);
                if (cls < NCLS) {
                    int ch = c0 + nt * 8 + 2 * gr + (i & 1);
                    atomicAdd(&g_sums[cls * CH + ch], acc[mt][nt][i]);
                }
            }
}

// ---------------------------------------------------------------------------
// keys: hist->counts, masked mean + L2 normalize. One block per class.
// Also zeroes out_loss (runs before lse).
// ---------------------------------------------------------------------------
__global__ void __launch_bounds__(256) keys_kernel(float* __restrict__ out_loss) {
    int k = blockIdx.x;
    int c = threadIdx.x;
    if (k == 0 && c == 0) *out_loss = 0.0f;

    __shared__ float red[8];
    __shared__ float snorm;
    __shared__ int   scnt;

    int h = 0;
    for (int i = c; i < SUMS_BLOCKS; i += 256) h += g_hist[i * NCLS + k];
    #pragma unroll
    for (int o = 16; o; o >>= 1) h += __shfl_xor_sync(0xffffffffu, h, o);
    if ((c & 31) == 0) red[c >> 5] = __int_as_float(h);
    __syncthreads();
    if (c == 0) {
        int t = 0;
        #pragma unroll
        for (int i = 0; i < 8; i++) t += __float_as_int(red[i]);
        g_counts[k] = t;
        scnt = max(t, 1);
    }
    __syncthreads();

    float v = g_sums[k * CH + c] / (float)scnt;

    float ss = v * v;
    #pragma unroll
    for (int o = 16; o; o >>= 1) ss += __shfl_xor_sync(0xffffffffu, ss, o);
    if ((c & 31) == 0) red[c >> 5] = ss;
    __syncthreads();
    if (c == 0) {
        float t = 0.0f;
        #pragma unroll
        for (int i = 0; i < 8; i++) t += red[i];
        snorm = fmaxf(sqrtf(t), 1e-12f);
    }
    __syncthreads();
    g_keys[k * CH + c] = v / snorm;
}

// ---------------------------------------------------------------------------
// lse + inline finalize: grid (CH, 2), 256 thr. Block (c, half) accumulates
// its j-range's 19 exp-sums and atomicAdds into g_lse. The SECOND-arriving
// block per (k,c) (atomicAdd returns old != 0 — partials are strictly
// positive, slot starts at 0) computes the final per-(k,c) loss term,
// resets the slot for the next replay, and adds to out_loss.
// Blocks (c<19, half=0) also re-zero g_sums for the next replay.
// ---------------------------------------------------------------------------
__global__ void __launch_bounds__(256) lse_kernel(const float* __restrict__ queues,
                                                  float* __restrict__ out_loss) {
    int c    = blockIdx.x;
    int half = blockIdx.y;
    int tid  = threadIdx.x;

    if (half == 0 && c < NCLS) g_sums[c * CH + tid] = 0.0f;

    __shared__ float sbb[NCLS];
    if (tid < NCLS) sbb[tid] = g_keys[tid * CH + c] * (INV_T * LOG2E);
    __syncthreads();

    float bb[NCLS];
    #pragma unroll
    for (int k = 0; k < NCLS; k++) bb[k] = sbb[k];

    const float* base = queues + (size_t)c * NQ;
    float s[NCLS];
    #pragma unroll
    for (int k = 0; k < NCLS; k++) s[k] = 0.0f;

    int jend = min(NQ, (half + 1) * NHALF);
    for (int j = half * NHALF + tid; j < jend; j += 256) {
        float q[NCLS];
        float qs = 0.0f;
        #pragma unroll
        for (int k = 0; k < NCLS; k++) {
            q[k] = base[(size_t)k * CH * NQ + j];
            qs += q[k];
        }
        #pragma unroll
        for (int k = 0; k < NCLS; k++) {
            float x = bb[k] * q[k];
            s[k] += ex2f(x) + ex2f(bb[k] * qs - x);
        }
    }

    __shared__ float wred[8][NCLS];
    int lane = tid & 31, wid = tid >> 5;
    #pragma unroll
    for (int k = 0; k < NCLS; k++) {
        float v = s[k];
        #pragma unroll
        for (int o = 16; o; o >>= 1) v += __shfl_xor_sync(0xffffffffu, v, o);
        if (lane == 0) wred[wid][k] = v;
    }
    __syncthreads();

    // first warp: publish partial, second-arriver finalizes
    if (tid < 32) {
        float part = 0.0f;
        if (tid < NCLS) {
            float tot = 0.0f;
            #pragma unroll
            for (int w = 0; w < 8; w++) tot += wred[w][tid];
            float old = atomicAdd(&g_lse[tid * CH + c], tot);
            if (old != 0.0f) {                      // I'm the completer
                float full = old + tot;
                g_lse[tid * CH + c] = 0.0f;         // reset for next replay
                if (g_counts[tid] > 0) {
                    float a  = g_keys[tid * CH + c] * INV_T;
                    float q0 = queues[((size_t)(tid * CH + c)) * NQ];
                    part = (__logf(full) - a * q0) * (1.0f / (float)CH);
                }
            }
        }
        #pragma unroll
        for (int o = 16; o; o >>= 1) part += __shfl_xor_sync(0xffffffffu, part, o);
        if (tid == 0 && part != 0.0f) atomicAdd(out_loss, part);
    }
}

// ---------------------------------------------------------------------------
extern "C" void kernel_launch(void* const* d_in, const int* in_sizes, int n_in,
                              void* d_out, int out_size) {
    const float *fea = nullptr, *res = nullptr, *queues = nullptr;
    for (int i = 0; i < n_in; i++) {
        if (in_sizes[i] == BSZ * CH * HW)        fea    = (const float*)d_in[i];
        else if (in_sizes[i] == BSZ * NCLS * HW) res    = (const float*)d_in[i];
        else if (in_sizes[i] == NCLS * CH * NQ)  queues = (const float*)d_in[i];
    }
    float* out      = (float*)d_out;
    float* out_loss = out + (size_t)BSZ * NCLS * HW;

    fused_kernel<<<dim3(KCHUNK, BSZ), 256>>>(res, out, fea);
    keys_kernel<<<NCLS, 256>>>(out_loss);
    lse_kernel<<<dim3(CH, 2), 256>>>(queues, out_loss);
}

// round 14
// speedup vs baseline: 1.8476x; 1.0008x over previous
#include <cuda_runtime.h>

#define NCLS 19
#define CH   256
#define HW   16384      // 128*128
#define BSZ  8
#define NQ   2975
#define INV_T 5.0f      // 1/0.2
#define LOG2E 1.44269504f

#define KCHUNK 64                 // pixel chunks per batch
#define CHUNK_PIX (HW/KCHUNK)     // 256
#define KSTEPS (CHUNK_PIX/8)      // 32
#define SUMS_BLOCKS (KCHUNK*BSZ)  // 512
#define NHALF 1488                // ceil(NQ/2)

// ---- device scratch. Protocol (kernel-boundary ordered, no tickets):
//  g_sums: zero at load; fused atomicAdds; keys reads; lse re-zeros.
//  g_lse : zero at load; lse atomicAdds; second-arriver reads+resets.
//  out_loss: keys zeroes; lse completers atomicAdd.
//  g_hist/g_counts/g_keys: overwrite semantics.
__device__ float g_sums[NCLS*CH];
__device__ float g_lse[NCLS*CH];
__device__ int   g_hist[SUMS_BLOCKS*NCLS];
__device__ int   g_counts[NCLS];
__device__ float g_keys[NCLS*CH];

__device__ __forceinline__ float ex2f(float x) {
    float r; asm("ex2.approx.f32 %0, %1;" : "=f"(r) : "f"(x)); return r;
}
__device__ __forceinline__ unsigned cvt_tf32(float x) {
    unsigned r; asm("cvt.rna.tf32.f32 %0, %1;" : "=r"(r) : "f"(x)); return r;
}
__device__ __forceinline__ void mma_tf32(float* d, const unsigned* a,
                                         unsigned b0, unsigned b1) {
    asm("mma.sync.aligned.m16n8k8.row.col.f32.tf32.tf32.f32 "
        "{%0,%1,%2,%3}, {%4,%5,%6,%7}, {%8,%9}, {%0,%1,%2,%3};"
        : "+f"(d[0]), "+f"(d[1]), "+f"(d[2]), "+f"(d[3])
        : "r"(a[0]), "r"(a[1]), "r"(a[2]), "r"(a[3]), "r"(b0), "r"(b1));
}

// ---------------------------------------------------------------------------
// fused pred + sums: block (chunk, b) owns 256 pixels x all 256 channels.
// Phase 1: per-pixel argmax over res + res->out copy + block hist.
// Phase 2: TF32 MMA masked pooling of fea, software-pipelined loads.
// ---------------------------------------------------------------------------
__global__ void __launch_bounds__(256) fused_kernel(const float* __restrict__ res,
                                                    float* __restrict__ out,
                                                    const float* __restrict__ fea) {
    int b      = blockIdx.y;
    int chunk  = blockIdx.x;
    int p_base = chunk * CHUNK_PIX;
    int tid  = threadIdx.x;

    __shared__ unsigned char spred[CHUNK_PIX];
    __shared__ int hist[NCLS];
    if (tid < NCLS) hist[tid] = 0;
    __syncthreads();

    // ---- phase 1: pred for pixel p_base + tid ----
    {
        const float* r = res + (size_t)b * NCLS * HW + p_base + tid;
        float*       o = out + (size_t)b * NCLS * HW + p_base + tid;
        float best = r[0];
        o[0] = best;
        int bk = 0;
        #pragma unroll
        for (int k = 1; k < NCLS; k++) {
            float v = r[(size_t)k * HW];
            o[(size_t)k * HW] = v;
            if (v > best) { best = v; bk = k; }
        }
        spred[tid] = (unsigned char)bk;
        atomicAdd(&hist[bk], 1);
    }
    __syncthreads();
    if (tid < NCLS) g_hist[(b * KCHUNK + chunk) * NCLS + tid] = hist[tid];

    // ---- phase 2: TF32 MMA pooling (pipelined) ----
    int warp = tid >> 5;
    int lane = tid & 31;
    int gq   = lane >> 2;
    int gr   = lane & 3;
    int c0   = warp * 32;

    float acc[2][4][4];
    #pragma unroll
    for (int mt = 0; mt < 2; mt++)
        #pragma unroll
        for (int nt = 0; nt < 4; nt++)
            #pragma unroll
            for (int i = 0; i < 4; i++) acc[mt][nt][i] = 0.0f;

    const float* base[4];
    #pragma unroll
    for (int nt = 0; nt < 4; nt++)
        base[nt] = fea + (size_t)(b * CH + c0 + nt * 8 + gq) * HW + p_base;

    // prologue loads for ks = 0
    float b0f[4], b1f[4];
    #pragma unroll
    for (int nt = 0; nt < 4; nt++) {
        b0f[nt] = base[nt][gr];
        b1f[nt] = base[nt][gr + 4];
    }

    for (int ks = 0; ks < KSTEPS; ks++) {
        int p = ks * 8;
        int pk0 = spred[p + gr];
        int pk1 = spred[p + gr + 4];

        // stash current batch, then issue next iteration's loads
        float c0f[4], c1f[4];
        #pragma unroll
        for (int nt = 0; nt < 4; nt++) { c0f[nt] = b0f[nt]; c1f[nt] = b1f[nt]; }
        if (ks + 1 < KSTEPS) {
            int pn = p + 8;
            #pragma unroll
            for (int nt = 0; nt < 4; nt++) {
                b0f[nt] = base[nt][pn + gr];
                b1f[nt] = base[nt][pn + gr + 4];
            }
        }

        unsigned au[2][4];
        #pragma unroll
        for (int mt = 0; mt < 2; mt++) {
            int cls = mt * 16 + gq;
            au[mt][0] = (pk0 == cls)     ? 0x3f800000u : 0u;
            au[mt][1] = (pk0 == cls + 8) ? 0x3f800000u : 0u;
            au[mt][2] = (pk1 == cls)     ? 0x3f800000u : 0u;
            au[mt][3] = (pk1 == cls + 8) ? 0x3f800000u : 0u;
        }

        #pragma unroll
        for (int nt = 0; nt < 4; nt++) {
            unsigned b0h = cvt_tf32(c0f[nt]);
            unsigned b1h = cvt_tf32(c1f[nt]);
            unsigned b0l = cvt_tf32(c0f[nt] - __uint_as_float(b0h));
            unsigned b1l = cvt_tf32(c1f[nt] - __uint_as_float(b1h));
            #pragma unroll
            for (int mt = 0; mt < 2; mt++) {
                mma_tf32(acc[mt][nt], au[mt], b0h, b1h);
                mma_tf32(acc[mt][nt], au[mt], b0l, b1l);
            }
        }
    }

    #pragma unroll
    for (int mt = 0; mt < 2; mt++)
        #pragma unroll
        for (int nt = 0; nt < 4; nt++)
            #pragma unroll
            for (int i = 0; i < 4; i++) {
                int cls = mt * 16 + gq + ((i >> 1) << 3);
                if (cls < NCLS) {
                    int ch = c0 + nt * 8 + 2 * gr + (i & 1);
                    atomicAdd(&g_sums[cls * CH + ch], acc[mt][nt][i]);
                }
            }
}

// ---------------------------------------------------------------------------
// keys: hist->counts, masked mean + L2 normalize. One block per class.
// Also zeroes out_loss (runs before lse).
// ---------------------------------------------------------------------------
__global__ void __launch_bounds__(256) keys_kernel(float* __restrict__ out_loss) {
    int k = blockIdx.x;
    int c = threadIdx.x;
    if (k == 0 && c == 0) *out_loss = 0.0f;

    __shared__ float red[8];
    __shared__ float snorm;
    __shared__ int   scnt;

    int h = 0;
    for (int i = c; i < SUMS_BLOCKS; i += 256) h += g_hist[i * NCLS + k];
    #pragma unroll
    for (int o = 16; o; o >>= 1) h += __shfl_xor_sync(0xffffffffu, h, o);
    if ((c & 31) == 0) red[c >> 5] = __int_as_float(h);
    __syncthreads();
    if (c == 0) {
        int t = 0;
        #pragma unroll
        for (int i = 0; i < 8; i++) t += __float_as_int(red[i]);
        g_counts[k] = t;
        scnt = max(t, 1);
    }
    __syncthreads();

    float v = g_sums[k * CH + c] / (float)scnt;

    float ss = v * v;
    #pragma unroll
    for (int o = 16; o; o >>= 1) ss += __shfl_xor_sync(0xffffffffu, ss, o);
    if ((c & 31) == 0) red[c >> 5] = ss;
    __syncthreads();
    if (c == 0) {
        float t = 0.0f;
        #pragma unroll
        for (int i = 0; i < 8; i++) t += red[i];
        snorm = fmaxf(sqrtf(t), 1e-12f);
    }
    __syncthreads();
    g_keys[k * CH + c] = v / snorm;
}

// ---------------------------------------------------------------------------
// lse + inline finalize: grid (CH, 2), 256 thr. Block (c, half) accumulates
// its j-range's 19 exp-sums and atomicAdds into g_lse. The SECOND-arriving
// block per (k,c) (atomicAdd returns old != 0 — partials are strictly
// positive, slot starts at 0) computes the final per-(k,c) loss term,
// resets the slot for the next replay, and adds to out_loss.
// Blocks (c<19, half=0) also re-zero g_sums for the next replay.
// ---------------------------------------------------------------------------
__global__ void __launch_bounds__(256) lse_kernel(const float* __restrict__ queues,
                                                  float* __restrict__ out_loss) {
    int c    = blockIdx.x;
    int half = blockIdx.y;
    int tid  = threadIdx.x;

    if (half == 0 && c < NCLS) g_sums[c * CH + tid] = 0.0f;

    __shared__ float sbb[NCLS];
    if (tid < NCLS) sbb[tid] = g_keys[tid * CH + c] * (INV_T * LOG2E);
    __syncthreads();

    float bb[NCLS];
    #pragma unroll
    for (int k = 0; k < NCLS; k++) bb[k] = sbb[k];

    const float* base = queues + (size_t)c * NQ;
    float s[NCLS];
    #pragma unroll
    for (int k = 0; k < NCLS; k++) s[k] = 0.0f;

    int jend = min(NQ, (half + 1) * NHALF);
    for (int j = half * NHALF + tid; j < jend; j += 256) {
        float q[NCLS];
        float qs = 0.0f;
        #pragma unroll
        for (int k = 0; k < NCLS; k++) {
            q[k] = base[(size_t)k * CH * NQ + j];
            qs += q[k];
        }
        #pragma unroll
        for (int k = 0; k < NCLS; k++) {
            float x = bb[k] * q[k];
            s[k] += ex2f(x) + ex2f(bb[k] * qs - x);
        }
    }

    __shared__ float wred[8][NCLS];
    int lane = tid & 31, wid = tid >> 5;
    #pragma unroll
    for (int k = 0; k < NCLS; k++) {
        float v = s[k];
        #pragma unroll
        for (int o = 16; o; o >>= 1) v += __shfl_xor_sync(0xffffffffu, v, o);
        if (lane == 0) wred[wid][k] = v;
    }
    __syncthreads();

    // first warp: publish partial, second-arriver finalizes
    if (tid < 32) {
        float part = 0.0f;
        if (tid < NCLS) {
            float tot = 0.0f;
            #pragma unroll
            for (int w = 0; w < 8; w++) tot += wred[w][tid];
            float old = atomicAdd(&g_lse[tid * CH + c], tot);
            if (old != 0.0f) {                      // I'm the completer
                float full = old + tot;
                g_lse[tid * CH + c] = 0.0f;         // reset for next replay
                if (g_counts[tid] > 0) {
                    float a  = g_keys[tid * CH + c] * INV_T;
                    float q0 = queues[((size_t)(tid * CH + c)) * NQ];
                    part = (__logf(full) - a * q0) * (1.0f / (float)CH);
                }
            }
        }
        #pragma unroll
        for (int o = 16; o; o >>= 1) part += __shfl_xor_sync(0xffffffffu, part, o);
        if (tid == 0 && part != 0.0f) atomicAdd(out_loss, part);
    }
}

// ---------------------------------------------------------------------------
extern "C" void kernel_launch(void* const* d_in, const int* in_sizes, int n_in,
                              void* d_out, int out_size) {
    const float *fea = nullptr, *res = nullptr, *queues = nullptr;
    for (int i = 0; i < n_in; i++) {
        if (in_sizes[i] == BSZ * CH * HW)        fea    = (const float*)d_in[i];
        else if (in_sizes[i] == BSZ * NCLS * HW) res    = (const float*)d_in[i];
        else if (in_sizes[i] == NCLS * CH * NQ)  queues = (const float*)d_in[i];
    }
    float* out      = (float*)d_out;
    float* out_loss = out + (size_t)BSZ * NCLS * HW;

    fused_kernel<<<dim3(KCHUNK, BSZ), 256>>>(res, out, fea);
    keys_kernel<<<NCLS, 256>>>(out_loss);
    lse_kernel<<<dim3(CH, 2), 256>>>(queues, out_loss);
}